// round 3
// baseline (speedup 1.0000x reference)
#include <cuda_runtime.h>
#include <math.h>

// Problem constants
#define NT 365
#define NS 300
#define NH 128
#define NG 32
#define NR 8
#define NROWS (NT*NS)          // 109500
#define KDIM 256
#define NDIM 384               // NH*3

// ---------------- scratch (device globals; no allocation in kernel_launch) --------
__device__ float g_H [NROWS*KDIM];       // tanh hidden of fcT, [row, k]
__device__ float g_Pl[NROWS*NH];         // rain per bucket
__device__ float g_Ev[NROWS*NH];         // evap per bucket
__device__ float g_vm[NROWS*NH];         // melt cap
__device__ float g_QS[NROWS*NH];         // q1+q2+q3
__device__ float g_CS[NROWS*NH];         // q1*cp/10 + q2*cs + q3*cg
__device__ float g_Ps [NROWS];           // snow precip (scalar per row)
__device__ float g_Plb[NROWS];           // P*(1-vf)
__device__ float g_cT[NS*KDIM];          // fcT layer1 static part (incl b1)
__device__ float g_cc[NS*NDIM];          // fcCT static part (incl bias)
__device__ float g_gates[NS*6*NH];       // kp,ks,kg,gp,gL,qb
__device__ float g_rg[NS*NH*NR];         // relu(r) * ga  (ga folded into taps)

// ======================= Kernel 1: per-site MLPs (fcW, fcR, statics) ==============
#define SB 6    // sites per block; 300/6 = 50 blocks
__global__ void __launch_bounds__(256) site_kernel(
    const float* __restrict__ xc,
    const float* __restrict__ fcR_w1, const float* __restrict__ fcR_b1,
    const float* __restrict__ fcR_w2, const float* __restrict__ fcR_b2,
    const float* __restrict__ fcW_w1, const float* __restrict__ fcW_b1,
    const float* __restrict__ fcW_w2, const float* __restrict__ fcW_b2,
    const float* __restrict__ fcT_w1, const float* __restrict__ fcT_b1,
    const float* __restrict__ fcCT_w, const float* __restrict__ fcCT_b)
{
    int s0  = blockIdx.x * SB;
    int tid = threadIdx.x;
    __shared__ float sxc[SB][32];
    __shared__ float hW [SB][257];
    __shared__ float hR [SB][257];
    __shared__ float sga[SB][128];

    for (int i = tid; i < SB*32; i += 256)
        sxc[i/32][i%32] = xc[(s0 + i/32)*32 + (i%32)];
    __syncthreads();

    // hidden layers (k = tid), plus fcT layer-1 static part
    {
        int k = tid;
        float aW[SB], aR[SB], aT[SB];
        #pragma unroll
        for (int s = 0; s < SB; s++) { aW[s]=0.f; aR[s]=0.f; aT[s]=0.f; }
        for (int j = 0; j < 32; j++) {
            float wW = fcW_w1[k*32 + j];
            float wR = fcR_w1[k*32 + j];
            float wT = fcT_w1[k*38 + 6 + j];
            #pragma unroll
            for (int s = 0; s < SB; s++) {
                float xv = sxc[s][j];
                aW[s] += wW*xv; aR[s] += wR*xv; aT[s] += wT*xv;
            }
        }
        float bW = fcW_b1[k], bR = fcR_b1[k], bT = fcT_b1[k];
        #pragma unroll
        for (int s = 0; s < SB; s++) {
            hW[s][k] = tanhf(aW[s] + bW);
            hR[s][k] = tanhf(aR[s] + bR);
            g_cT[(s0+s)*KDIM + k] = aT[s] + bT;
        }
    }
    // fcCT static part (only depends on sxc)
    for (int o = tid; o < NDIM; o += 256) {
        float acc[SB];
        float b = fcCT_b[o];
        #pragma unroll
        for (int s = 0; s < SB; s++) acc[s] = b;
        for (int j = 0; j < 32; j++) {
            float w = fcCT_w[o*34 + 2 + j];
            #pragma unroll
            for (int s = 0; s < SB; s++) acc[s] += w * sxc[s][j];
        }
        #pragma unroll
        for (int s = 0; s < SB; s++) g_cc[(s0+s)*NDIM + o] = acc[s];
    }
    __syncthreads();

    // fcW layer 2 -> gates
    for (int o = tid; o < 7*NH; o += 256) {
        float acc[SB];
        float b = fcW_b2[o];
        #pragma unroll
        for (int s = 0; s < SB; s++) acc[s] = b;
        for (int k = 0; k < KDIM; k++) {
            float w = fcW_w2[o*KDIM + k];
            #pragma unroll
            for (int s = 0; s < SB; s++) acc[s] += w * hW[s][k];
        }
        int g = o >> 7, h = o & 127;
        #pragma unroll
        for (int s = 0; s < SB; s++) {
            float a = acc[s];
            if      (g < 4)  g_gates[(s0+s)*6*NH + g*NH + h] = 1.f/(1.f + expf(-a));
            else if (g == 4) g_gates[(s0+s)*6*NH + 4*NH + h] = expf(a)*2.f;
            else if (g == 5) g_gates[(s0+s)*6*NH + 5*NH + h] = fmaxf(a, 0.f);
            else             sga[s][h] = a;
        }
    }
    __syncthreads();

    // softmax over h (one thread per site)
    if (tid < SB) {
        float m = -1e30f;
        for (int h = 0; h < NH; h++) m = fmaxf(m, sga[tid][h]);
        float sum = 0.f;
        for (int h = 0; h < NH; h++) { float e = expf(sga[tid][h] - m); sga[tid][h] = e; sum += e; }
        float inv = 1.f / sum;
        for (int h = 0; h < NH; h++) sga[tid][h] *= inv;
    }
    __syncthreads();

    // fcR layer 2 -> taps, fold ga
    for (int o = tid; o < NH*NR; o += 256) {
        float acc[SB];
        float b = fcR_b2[o];
        #pragma unroll
        for (int s = 0; s < SB; s++) acc[s] = b;
        for (int k = 0; k < KDIM; k++) {
            float w = fcR_w2[o*KDIM + k];
            #pragma unroll
            for (int s = 0; s < SB; s++) acc[s] += w * hR[s][k];
        }
        int h = o >> 3;
        #pragma unroll
        for (int s = 0; s < SB; s++)
            g_rg[(s0+s)*NH*NR + o] = fmaxf(acc[s], 0.f) * sga[s][h];
    }
}

// =================== Kernel 2a: fcT layer-1 dynamic part (+ snow split) ===========
__global__ void __launch_bounds__(256) hidden_kernel(
    const float* __restrict__ x, const float* __restrict__ fcT_w1)
{
    int rm = blockIdx.x;             // row = t*NS + s
    int k  = threadIdx.x;            // hidden unit
    int s  = rm % NS;
    const float* xr = x + (size_t)rm*6;
    float acc = 0.f;
    #pragma unroll
    for (int j = 0; j < 6; j++) acc += fcT_w1[k*38 + j] * xr[j];
    g_H[(size_t)rm*KDIM + k] = tanhf(acc + g_cT[s*KDIM + k]);

    if (k == 0) {
        float P = xr[0], T1 = xr[2], T2 = xr[3];
        float d = T2 - T1;
        float ratio = (T1 + T2) / (d == 0.f ? 1.f : d);
        ratio = fminf(fmaxf(ratio, -1.f), 1.f);
        float vf = acosf(ratio) / 3.1415f;
        if (T1 >= 0.f) vf = 0.f;
        else if (T2 <= 0.f) vf = 1.f;
        g_Ps [rm] = P * vf;
        g_Plb[rm] = P * (1.f - vf);
    }
}

// ============ Kernel 2b: fcT layer-2 SGEMM (fused activation epilogue) ============
// C[row, n] = sum_k H[row,k] * W2[n,k];  n-tile of 128 == one output group.
__global__ void __launch_bounds__(256) fct_gemm_kernel(
    const float* __restrict__ W2, const float* __restrict__ b2,
    const float* __restrict__ x)
{
    __shared__ float As[8][128];
    __shared__ float Bs[8][132];

    int g   = blockIdx.y;                 // 0: Pl(vi), 1: Ev(ve), 2: vm
    int tid = threadIdx.x;
    int tx  = tid & 15, ty = tid >> 4;
    int rowBase = blockIdx.x * 128;
    int nBase   = g * 128;

    float acc[8][8];
    #pragma unroll
    for (int i = 0; i < 8; i++)
        #pragma unroll
        for (int j = 0; j < 8; j++) acc[i][j] = 0.f;

    int lr   = tid >> 1;        // 0..127
    int half = tid & 1;         // which float4 of the BK=8 slice

    for (int k0 = 0; k0 < KDIM; k0 += 8) {
        int grow = rowBase + lr;
        float4 av = make_float4(0.f,0.f,0.f,0.f);
        if (grow < NROWS)
            av = *(const float4*)&g_H[(size_t)grow*KDIM + k0 + half*4];
        As[half*4+0][lr] = av.x; As[half*4+1][lr] = av.y;
        As[half*4+2][lr] = av.z; As[half*4+3][lr] = av.w;

        float4 bv = *(const float4*)&W2[(size_t)(nBase + lr)*KDIM + k0 + half*4];
        Bs[half*4+0][lr] = bv.x; Bs[half*4+1][lr] = bv.y;
        Bs[half*4+2][lr] = bv.z; Bs[half*4+3][lr] = bv.w;
        __syncthreads();

        #pragma unroll
        for (int kk = 0; kk < 8; kk++) {
            float a[8], b[8];
            #pragma unroll
            for (int i = 0; i < 4; i++) { a[i]   = As[kk][ty*8+i];   a[i+4] = As[kk][ty*8+4+i]; }
            #pragma unroll
            for (int j = 0; j < 4; j++) { b[j]   = Bs[kk][tx*8+j];   b[j+4] = Bs[kk][tx*8+4+j]; }
            #pragma unroll
            for (int i = 0; i < 8; i++)
                #pragma unroll
                for (int j = 0; j < 8; j++)
                    acc[i][j] += a[i]*b[j];
        }
        __syncthreads();
    }

    // epilogue: whole block is one group g
    #pragma unroll
    for (int i = 0; i < 8; i++) {
        int rm = rowBase + ty*8 + i;
        if (rm >= NROWS) continue;
        float rowScale = 0.f;
        if      (g == 0) rowScale = g_Plb[rm];          // P*(1-vf)
        else if (g == 1) rowScale = x[(size_t)rm*6 + 1]; // E
        #pragma unroll
        for (int j = 0; j < 8; j++) {
            int h = tx*8 + j;
            float val = acc[i][j] + b2[nBase + h];
            size_t o = (size_t)rm*NH + h;
            if (g == 0) {
                float vi = fminf(fmaxf(val*2.f/6.f + 0.5f, 0.f), 1.f);  // hardsigmoid(2v)
                g_Pl[o] = rowScale * vi;
            } else if (g == 1) {
                g_Ev[o] = rowScale * fmaxf(val, 0.f) * 2.f;
            } else {
                g_vm[o] = expf(val);
            }
        }
    }
}

// ========================= Kernel 3: sequential bucket scan =======================
__global__ void __launch_bounds__(128) scan_kernel(
    const float* __restrict__ x, const float* __restrict__ fcCT_w)
{
    int s = blockIdx.x, h = threadIdx.x;
    const float* G = g_gates + s*6*NH;
    float kp = G[0*NH+h], ksv = G[1*NH+h], kg = G[2*NH+h];
    float gp = G[3*NH+h], gL  = G[4*NH+h], qb = G[5*NH+h];
    float cc0 = g_cc[s*NDIM + h];
    float cc1 = g_cc[s*NDIM + NH + h];
    float cc2 = g_cc[s*NDIM + 2*NH + h];
    float wp1 = fcCT_w[(h)*34 + 0],      wp2 = fcCT_w[(h)*34 + 1];
    float ws1 = fcCT_w[(NH+h)*34 + 0],   ws2 = fcCT_w[(NH+h)*34 + 1];
    float wg1 = fcCT_w[(2*NH+h)*34 + 0], wg2 = fcCT_w[(2*NH+h)*34 + 1];

    float Sf = 0.f, Ss = 0.f, Sg = 0.f;
    int base = s*NH + h;
    float pl = g_Pl[base], ev = g_Ev[base], vmv = g_vm[base];

    for (int t = 0; t < NT; t++) {
        int rm = t*NS + s;
        float Psv = g_Ps[rm];
        float T1  = x[(size_t)rm*6 + 2];
        float T2  = x[(size_t)rm*6 + 3];
        // prefetch next timestep's per-bucket inputs
        float pl_n = 0.f, ev_n = 0.f, vm_n = 0.f;
        if (t < NT-1) {
            int idxn = (t+1)*NS*NH + base;
            pl_n = g_Pl[idxn]; ev_n = g_Ev[idxn]; vm_n = g_vm[idxn];
        }

        float a  = Sf + Psv;
        float qf = fminf(a, vmv);
        Sf = fmaxf(a - vmv, 0.f);
        float H  = fmaxf(Ss + pl + qf - ev, 0.f);
        float qp = fmaxf(kp*(H - gL), 0.f);
        float qs = ksv * fminf(H, gL);
        Ss = H - qp - qs;
        float qso = qs*(1.f - gp);
        float qsg = qs*gp;
        float sg2 = Sg + qsg;
        float qg  = kg*sg2 + qb;
        Sg = (1.f - kg)*sg2 - qb;

        float cp = expf(cc0 + T1*wp1 + T2*wp2);
        float cs = expf(cc1 + T1*ws1 + T2*ws2);
        float cg = expf(cc2 + T1*wg1 + T2*wg2);

        int idx = t*NS*NH + base;
        g_QS[idx] = qp + qso + qg;
        g_CS[idx] = qp*cp*0.1f + qso*cs + qg*cg;

        pl = pl_n; ev = ev_n; vmv = vm_n;
    }
}

// ================== Kernel 4: routed conv + ga-reduction + outputs ================
// Ring invariant at loop entry for time t: qh[j] == Q[t-1-j] for j=0..6.
// Body: shift (qh[i]=qh[i-1], i=7..1) -> qh[i]==Q[t-i]; then qh[0]=Q[t].
#define TT 73   // 365 = 5*73
__global__ void __launch_bounds__(128) conv_kernel(float* __restrict__ out)
{
    int chunk = blockIdx.x, s = blockIdx.y, h = threadIdx.x;
    int t0 = chunk * TT;

    float rg[NR];
    #pragma unroll
    for (int i = 0; i < NR; i++) rg[i] = g_rg[s*NH*NR + h*NR + i];

    float qh[NR], ch[NR];
    // preload history: qh[j] = Q[t0-1-j] for j=0..6 (position 7 is overwritten
    // by the first shift before it is ever read)
    #pragma unroll
    for (int j = 0; j < NR-1; j++) {
        int t = t0 - 1 - j;
        if (t >= 0) {
            int idx = t*NS*NH + s*NH + h;
            qh[j] = g_QS[idx]; ch[j] = g_CS[idx];
        } else { qh[j] = 0.f; ch[j] = 0.f; }
    }
    qh[NR-1] = 0.f; ch[NR-1] = 0.f;

    __shared__ float sQ[4], sC[4];
    int lane = h & 31, warp = h >> 5;

    for (int tt = 0; tt < TT; tt++) {
        int t = t0 + tt;
        #pragma unroll
        for (int i = NR-1; i >= 1; i--) { qh[i] = qh[i-1]; ch[i] = ch[i-1]; }
        int idx = t*NS*NH + s*NH + h;
        qh[0] = g_QS[idx]; ch[0] = g_CS[idx];

        float pq = 0.f, pc = 0.f;
        #pragma unroll
        for (int i = 0; i < NR; i++) { pq += qh[i]*rg[i]; pc += ch[i]*rg[i]; }

        #pragma unroll
        for (int o = 16; o; o >>= 1) {
            pq += __shfl_down_sync(0xffffffffu, pq, o);
            pc += __shfl_down_sync(0xffffffffu, pc, o);
        }
        if (lane == 0) { sQ[warp] = pq; sC[warp] = pc; }
        __syncthreads();
        if (h == 0) {
            float q = sQ[0]+sQ[1]+sQ[2]+sQ[3];
            float c = sC[0]+sC[1]+sC[2]+sC[3];
            out[t*NS + s]          = q;      // outQ
            out[NROWS + t*NS + s]  = c / q;  // outC
        }
        __syncthreads();
    }
}

// ==================================== launch ======================================
extern "C" void kernel_launch(void* const* d_in, const int* in_sizes, int n_in,
                              void* d_out, int out_size)
{
    const float* x       = (const float*)d_in[0];
    const float* xc      = (const float*)d_in[1];
    const float* fcR_w1  = (const float*)d_in[2];
    const float* fcR_b1  = (const float*)d_in[3];
    const float* fcR_w2  = (const float*)d_in[4];
    const float* fcR_b2  = (const float*)d_in[5];
    const float* fcW_w1  = (const float*)d_in[6];
    const float* fcW_b1  = (const float*)d_in[7];
    const float* fcW_w2  = (const float*)d_in[8];
    const float* fcW_b2  = (const float*)d_in[9];
    const float* fcT_w1  = (const float*)d_in[10];
    const float* fcT_b1  = (const float*)d_in[11];
    const float* fcT_w2  = (const float*)d_in[12];
    const float* fcT_b2  = (const float*)d_in[13];
    const float* fcCT_w  = (const float*)d_in[14];
    const float* fcCT_b  = (const float*)d_in[15];
    float* out = (float*)d_out;

    site_kernel<<<NS/SB, 256>>>(xc, fcR_w1, fcR_b1, fcR_w2, fcR_b2,
                                fcW_w1, fcW_b1, fcW_w2, fcW_b2,
                                fcT_w1, fcT_b1, fcCT_w, fcCT_b);
    hidden_kernel<<<NROWS, 256>>>(x, fcT_w1);
    dim3 gg((NROWS + 127)/128, 3);
    fct_gemm_kernel<<<gg, 256>>>(fcT_w2, fcT_b2, x);
    scan_kernel<<<NS, 128>>>(x, fcCT_w);
    dim3 gc(NT/TT, NS);
    conv_kernel<<<gc, 128>>>(out);
}